// round 15
// baseline (speedup 1.0000x reference)
#include <cuda_runtime.h>

// SpikeLayer: T=16 timesteps, per-step batch B=512, features D=8192.
// For each (b, d): V += x[t]; if |V| > 1 -> V = 0; out[t] = V.
//
// R14: 256-bit global accesses (sm_100+ ld/st.global.v8.f32 -> LDG.E.256 /
// STG.E.256). Same one-pass layout as the converged GRP=4 winner, but each
// thread owns 8 floats per timestep: halves memory-instruction count and
// doubles per-warp contiguous burst length, targeting the DRAM R/W
// scheduling efficiency stuck at ~80%.

#define TT 16
#define BB 512
#define DD 8192
#define STRIDE8 ((BB * DD) / 8)   // float8 per timestep slab = 524,288
#define GRP 4
#define TPB 256

__device__ __forceinline__ void ldg256_cs(const float* __restrict__ p, float* v)
{
    asm volatile(
        "ld.global.cs.v8.f32 {%0,%1,%2,%3,%4,%5,%6,%7}, [%8];"
        : "=f"(v[0]), "=f"(v[1]), "=f"(v[2]), "=f"(v[3]),
          "=f"(v[4]), "=f"(v[5]), "=f"(v[6]), "=f"(v[7])
        : "l"(p));
}

__device__ __forceinline__ void stg256_cs(float* __restrict__ p, const float* v)
{
    asm volatile(
        "st.global.cs.v8.f32 [%0], {%1,%2,%3,%4,%5,%6,%7,%8};"
        :: "l"(p),
           "f"(v[0]), "f"(v[1]), "f"(v[2]), "f"(v[3]),
           "f"(v[4]), "f"(v[5]), "f"(v[6]), "f"(v[7])
        : "memory");
}

__global__ __launch_bounds__(TPB) void spike_kernel(
    const float* __restrict__ in, float* __restrict__ out)
{
    const unsigned idx = blockIdx.x * (unsigned)TPB + threadIdx.x;  // 0 .. STRIDE8-1
    const float* __restrict__ p = in  + (size_t)idx * 8;
    float*       __restrict__ q = out + (size_t)idx * 8;

    float V[8];
#pragma unroll
    for (int i = 0; i < 8; ++i) V[i] = 0.0f;

    float x[GRP][8];

#pragma unroll
    for (int g = 0; g < TT / GRP; ++g) {
        // Batch GRP 256-bit streaming loads
#pragma unroll
        for (int t = 0; t < GRP; ++t)
            ldg256_cs(p + (size_t)(g * GRP + t) * (STRIDE8 * 8), x[t]);

        // Dependency chain in registers; overwrite x[] with outputs
#pragma unroll
        for (int t = 0; t < GRP; ++t) {
#pragma unroll
            for (int i = 0; i < 8; ++i) {
                V[i] += x[t][i];
                V[i] = (fabsf(V[i]) > 1.0f) ? 0.0f : V[i];
                x[t][i] = V[i];
            }
        }

        // Batch GRP 256-bit streaming stores
#pragma unroll
        for (int t = 0; t < GRP; ++t)
            stg256_cs(q + (size_t)(g * GRP + t) * (STRIDE8 * 8), x[t]);
    }
}

extern "C" void kernel_launch(void* const* d_in, const int* in_sizes, int n_in,
                              void* d_out, int out_size)
{
    (void)in_sizes; (void)n_in; (void)out_size;
    const float* in  = (const float*)d_in[0];
    float*       out = (float*)d_out;

    const int blocks = STRIDE8 / TPB;  // 2048
    spike_kernel<<<blocks, TPB>>>(in, out);
}

// round 16
// speedup vs baseline: 1.0267x; 1.0267x over previous
#include <cuda_runtime.h>

// SpikeLayer: T=16 timesteps, per-step batch B=512, features D=8192.
// For each (b, d): V += x[t]; if |V| > 1 -> V = 0; out[t] = V.
//
// FINAL (R15): HBM mixed read/write ceiling, proven across 8 variants:
// GRP {16,8,4,2} -> {77.5,76.7,75.6,76.7} us; TPB {256,512} -> {75.6,76.1};
// persistent grid 85.6 (regression); SW pipeline 75.5 (neutral);
// 256-bit LDG/STG 76.5 (neutral). DRAM pinned 79-81%, occ 43-88% with zero
// perf correlation -> throughput-limited at the DRAM R/W-interleave
// efficiency floor (~6.35 TB/s counted / ~7.0 TB/s effective of 8 TB/s).
// Locked-in measured best: one-pass float4/thread, GRP=4 batched
// load/compute/store, streaming (.cs) hints, 4096 CTAs x 256 threads.

#define TT 16
#define BB 512
#define DD 8192
#define STRIDE4 ((BB * DD) / 4)   // float4 per timestep slab = 1,048,576
#define GRP 4

__global__ __launch_bounds__(256) void spike_kernel(
    const float4* __restrict__ in, float4* __restrict__ out)
{
    const unsigned idx = blockIdx.x * 256u + threadIdx.x;  // 0 .. STRIDE4-1
    const float4* __restrict__ p = in  + idx;
    float4*       __restrict__ q = out + idx;

    float4 V = make_float4(0.f, 0.f, 0.f, 0.f);
    float4 x[GRP];

#pragma unroll
    for (int g = 0; g < TT / GRP; ++g) {
        // Batch 4 streaming loads
#pragma unroll
        for (int t = 0; t < GRP; ++t)
            x[t] = __ldcs(p + (unsigned)(g * GRP + t) * STRIDE4);

        // Dependency chain in registers; overwrite x[] with outputs
#pragma unroll
        for (int t = 0; t < GRP; ++t) {
            V.x += x[t].x;  V.x = (fabsf(V.x) > 1.0f) ? 0.0f : V.x;
            V.y += x[t].y;  V.y = (fabsf(V.y) > 1.0f) ? 0.0f : V.y;
            V.z += x[t].z;  V.z = (fabsf(V.z) > 1.0f) ? 0.0f : V.z;
            V.w += x[t].w;  V.w = (fabsf(V.w) > 1.0f) ? 0.0f : V.w;
            x[t] = V;
        }

        // Batch 4 streaming stores
#pragma unroll
        for (int t = 0; t < GRP; ++t)
            __stcs(q + (unsigned)(g * GRP + t) * STRIDE4, x[t]);
    }
}

extern "C" void kernel_launch(void* const* d_in, const int* in_sizes, int n_in,
                              void* d_out, int out_size)
{
    (void)in_sizes; (void)n_in; (void)out_size;
    const float4* in  = (const float4*)d_in[0];
    float4*       out = (float4*)d_out;

    const int threads = 256;
    const int blocks  = STRIDE4 / threads;  // 4096
    spike_kernel<<<blocks, threads>>>(in, out);
}

// round 17
// speedup vs baseline: 1.0283x; 1.0016x over previous
#include <cuda_runtime.h>

// SpikeLayer: T=16 timesteps, per-step batch B=512, features D=8192.
// For each (b, d): V += x[t]; if |V| > 1 -> V = 0; out[t] = V.
//
// FINAL (converged R16): HBM mixed read/write ceiling, proven across 10
// variants over the session:
//   GRP {16,8,4,2} -> {77.5,76.7,75.6,76.7} us      (batch=4 best)
//   TPB {256,512} -> {75.6,76.1}                    (256 best)
//   grid {4096 waves, 1024 persistent} -> {75.6,85.6} (full grid required)
//   SW pipeline -> 75.5 (neutral); 256-bit LDG/STG -> 76.5 (neutral);
//   occupancy 43-88% uncorrelated with perf.
// DRAM pinned 79-81% (~6.4 TB/s counted, ~7.0 TB/s effective of 8 TB/s
// spec) on 512 MiB of irreducible zero-reuse fp32 traffic. Repeated-config
// spread == cross-config spread -> at the hardware floor.
//
// Locked-in best: one-pass float4/thread, GRP=4 batched load/compute/store,
// streaming (.cs) hints, 4096 CTAs x 256 threads.

#define TT 16
#define BB 512
#define DD 8192
#define STRIDE4 ((BB * DD) / 4)   // float4 per timestep slab = 1,048,576
#define GRP 4

__global__ __launch_bounds__(256) void spike_kernel(
    const float4* __restrict__ in, float4* __restrict__ out)
{
    const unsigned idx = blockIdx.x * 256u + threadIdx.x;  // 0 .. STRIDE4-1
    const float4* __restrict__ p = in  + idx;
    float4*       __restrict__ q = out + idx;

    float4 V = make_float4(0.f, 0.f, 0.f, 0.f);
    float4 x[GRP];

#pragma unroll
    for (int g = 0; g < TT / GRP; ++g) {
        // Batch 4 streaming loads
#pragma unroll
        for (int t = 0; t < GRP; ++t)
            x[t] = __ldcs(p + (unsigned)(g * GRP + t) * STRIDE4);

        // Dependency chain in registers; overwrite x[] with outputs
#pragma unroll
        for (int t = 0; t < GRP; ++t) {
            V.x += x[t].x;  V.x = (fabsf(V.x) > 1.0f) ? 0.0f : V.x;
            V.y += x[t].y;  V.y = (fabsf(V.y) > 1.0f) ? 0.0f : V.y;
            V.z += x[t].z;  V.z = (fabsf(V.z) > 1.0f) ? 0.0f : V.z;
            V.w += x[t].w;  V.w = (fabsf(V.w) > 1.0f) ? 0.0f : V.w;
            x[t] = V;
        }

        // Batch 4 streaming stores
#pragma unroll
        for (int t = 0; t < GRP; ++t)
            __stcs(q + (unsigned)(g * GRP + t) * STRIDE4, x[t]);
    }
}

extern "C" void kernel_launch(void* const* d_in, const int* in_sizes, int n_in,
                              void* d_out, int out_size)
{
    (void)in_sizes; (void)n_in; (void)out_size;
    const float4* in  = (const float4*)d_in[0];
    float4*       out = (float4*)d_out;

    const int threads = 256;
    const int blocks  = STRIDE4 / threads;  // 4096
    spike_kernel<<<blocks, threads>>>(in, out);
}